// round 5
// baseline (speedup 1.0000x reference)
#include <cuda_runtime.h>
#include <math.h>
#include <stdint.h>

#define TT 4096   // tokens (B*S)
#define HH 1024   // hidden
#define II 2048   // intermediate
#define EE 8      // experts
// TOP_K = 2

// -------- scratch (static device arrays: no allocs allowed) --------
__device__ int   g_cnt[EE];
__device__ float g_psum[EE];
__device__ float g_zsum;
__device__ int   g_tok[EE * TT];          // bucket -> token
__device__ int   g_tslot[TT * 2];         // token -> slot (e*TT+pos)
__device__ float g_tw[TT * 2];            // token -> normalized weight
__device__ float g_act_sh[(size_t)TT * II];          // shared-expert activations (tf32 bits)
__device__ float g_act_rt[(size_t)EE * TT * II];     // routed activations (tf32 bits)
__device__ float g_out2[(size_t)EE * TT * HH];       // routed down-proj, slot-major

// pre-rounded tf32 copies (bit patterns stored as float)
__device__ float g_w_gate[(size_t)EE * HH * II];
__device__ float g_w_up[(size_t)EE * HH * II];
__device__ float g_w_down[(size_t)EE * II * HH];
__device__ float g_w_sg[(size_t)HH * II];
__device__ float g_w_su[(size_t)HH * II];
__device__ float g_w_sd[(size_t)II * HH];
__device__ float g_x32[(size_t)TT * HH];

// -------------------- helpers --------------------
__device__ __forceinline__ uint32_t f2tf(float f) {
    uint32_t o; asm("cvt.rna.tf32.f32 %0, %1;" : "=r"(o) : "f"(f)); return o;
}
__device__ __forceinline__ void ldsm4(uint32_t& r0, uint32_t& r1, uint32_t& r2, uint32_t& r3,
                                      uint32_t addr) {
    asm volatile("ldmatrix.sync.aligned.m8n8.x4.shared.b16 {%0,%1,%2,%3}, [%4];"
                 : "=r"(r0), "=r"(r1), "=r"(r2), "=r"(r3) : "r"(addr));
}
__device__ __forceinline__ void mma_tf32(float* c, const uint32_t* a, uint32_t b0, uint32_t b1) {
    asm volatile("mma.sync.aligned.m16n8k8.row.col.f32.tf32.tf32.f32 "
                 "{%0,%1,%2,%3}, {%4,%5,%6,%7}, {%8,%9}, {%0,%1,%2,%3};"
                 : "+f"(c[0]), "+f"(c[1]), "+f"(c[2]), "+f"(c[3])
                 : "r"(a[0]), "r"(a[1]), "r"(a[2]), "r"(a[3]), "r"(b0), "r"(b1));
}
__device__ __forceinline__ void cp_async16(uint32_t saddr, const void* gptr) {
    asm volatile("cp.async.cg.shared.global [%0], [%1], 16;" :: "r"(saddr), "l"(gptr));
}
__device__ __forceinline__ void cp_commit() { asm volatile("cp.async.commit_group;"); }
template<int N>
__device__ __forceinline__ void cp_wait() { asm volatile("cp.async.wait_group %0;" :: "n"(N)); }

// -------------------- init --------------------
__global__ void k_init() {
    int i = threadIdx.x;
    if (i < EE) { g_cnt[i] = 0; g_psum[i] = 0.f; }
    if (i == 0) g_zsum = 0.f;
}

// -------------------- pre-round weights + x to tf32 --------------------
// all chunk sizes are powers of two (in float4 units):
#define N4_E (EE * HH * II / 4)   // 2^22 per expert-weight tensor
#define N4_S (HH * II / 4)        // 2^19 per shared-weight tensor
#define N4_X (TT * HH / 4)        // 2^20 for x
#define N4_TOTAL (3 * N4_E + 3 * N4_S + N4_X)

__global__ __launch_bounds__(256) void k_round(
    const float* __restrict__ gw, const float* __restrict__ uw, const float* __restrict__ dw,
    const float* __restrict__ sg, const float* __restrict__ su, const float* __restrict__ sd,
    const float* __restrict__ x)
{
    size_t i = (size_t)blockIdx.x * 256 + threadIdx.x;
    if (i >= N4_TOTAL) return;
    const float* src;
    float* dst;
    size_t off;
    if (i < (size_t)3 * N4_E) {
        int b = (int)(i >> 22);
        off = i & (N4_E - 1);
        src = (b == 0) ? gw : (b == 1) ? uw : dw;
        dst = (b == 0) ? g_w_gate : (b == 1) ? g_w_up : g_w_down;
    } else if (i < (size_t)3 * N4_E + 3 * N4_S) {
        size_t j = i - (size_t)3 * N4_E;
        int b = (int)(j >> 19);
        off = j & (N4_S - 1);
        src = (b == 0) ? sg : (b == 1) ? su : sd;
        dst = (b == 0) ? g_w_sg : (b == 1) ? g_w_su : g_w_sd;
    } else {
        off = i - ((size_t)3 * N4_E + 3 * N4_S);
        src = x;
        dst = g_x32;
    }
    float4 v = ((const float4*)src)[off];
    uint4 o = make_uint4(f2tf(v.x), f2tf(v.y), f2tf(v.z), f2tf(v.w));
    ((uint4*)dst)[off] = o;
}

// -------------------- router (full fp32 precision) --------------------
__global__ void k_router(const float* __restrict__ x, const float* __restrict__ rw,
                         float* __restrict__ out) {
    __shared__ float s_p[EE];
    __shared__ float s_z;
    if (threadIdx.x < EE) s_p[threadIdx.x] = 0.f;
    if (threadIdx.x == 0) s_z = 0.f;
    __syncthreads();

    const int warp = threadIdx.x >> 5;
    const int lane = threadIdx.x & 31;
    const int t = blockIdx.x * 4 + warp;

    float acc[EE];
#pragma unroll
    for (int e = 0; e < EE; e++) acc[e] = 0.f;
    const float* xr = x + (size_t)t * HH;
    for (int jj = 0; jj < HH / 32; jj++) {
        int j = jj * 32 + lane;
        float xv = xr[j];
        const float* r = rw + j * EE;
#pragma unroll
        for (int e = 0; e < EE; e++) acc[e] = fmaf(xv, r[e], acc[e]);
    }
#pragma unroll
    for (int e = 0; e < EE; e++) {
#pragma unroll
        for (int o = 16; o > 0; o >>= 1) acc[e] += __shfl_xor_sync(0xffffffffu, acc[e], o);
    }

    if (lane == 0) {
        float* lo = out + (size_t)TT * HH + 2 + (size_t)t * EE;
        float mx = acc[0];
#pragma unroll
        for (int e = 1; e < EE; e++) mx = fmaxf(mx, acc[e]);
        float p[EE];
        float se = 0.f;
#pragma unroll
        for (int e = 0; e < EE; e++) { p[e] = expf(acc[e] - mx); se += p[e]; }
        float lse = logf(se) + mx;
        atomicAdd(&s_z, lse * lse);
        float inv = 1.f / se;
#pragma unroll
        for (int e = 0; e < EE; e++) {
            p[e] *= inv;
            lo[e] = acc[e];
            atomicAdd(&s_p[e], p[e]);
        }
        int i0 = 0;
#pragma unroll
        for (int e = 1; e < EE; e++) if (p[e] > p[i0]) i0 = e;
        int i1 = -1;
#pragma unroll
        for (int e = 0; e < EE; e++) {
            if (e == i0) continue;
            if (i1 < 0 || p[e] > p[i1]) i1 = e;
        }
        float ws = p[i0] + p[i1];
        float w0 = p[i0] / ws, w1 = p[i1] / ws;
        int pos0 = atomicAdd(&g_cnt[i0], 1);
        g_tok[i0 * TT + pos0] = t;
        g_tslot[t * 2 + 0] = i0 * TT + pos0; g_tw[t * 2 + 0] = w0;
        int pos1 = atomicAdd(&g_cnt[i1], 1);
        g_tok[i1 * TT + pos1] = t;
        g_tslot[t * 2 + 1] = i1 * TT + pos1; g_tw[t * 2 + 1] = w1;
    }
    __syncthreads();
    if (threadIdx.x < EE) atomicAdd(&g_psum[threadIdx.x], s_p[threadIdx.x]);
    if (threadIdx.x == 0) atomicAdd(&g_zsum, s_z);
}

// ==================== tf32 GEMM, 3-stage cp.async pipeline ====================
// All operands pre-rounded to tf32 bit patterns — NO cvt in the mainloop.
// BM=128, BN=64, BK=32. 256 threads = 8 warps (4m x 2n), warp tile 32x32.
// MODE 0: fused gate+up — A = g_x32 (gathered), B0 = g_w_gate, B1 = g_w_up,
//         epilogue silu(g)*u rounded to tf32 -> act buf.
// MODE 1: down — A = act buf (already tf32), B0 = g_w_down,
//         z<8: store g_out2 slot-major; z==8: store out.
#define AW 36
#define BW 72
#define ABUF (128 * AW)
#define BBUF (32 * BW)
#define NSTAGE 3

template<int MODE>
__global__ __launch_bounds__(256) void k_gemm(float* __restrict__ out)
{
    constexpr int KD = (MODE == 1) ? II : HH;
    constexpr int ND = (MODE == 1) ? HH : II;
    constexpr int NK = KD / 32;
    constexpr int NB = (MODE == 0) ? 2 : 1;
    constexpr int STAGE = ABUF + NB * BBUF;

    const int e = blockIdx.z;
    const bool sp = (e == EE);
    const int nrows = sp ? TT : g_cnt[e];
    const int m0 = blockIdx.y * 128;
    if (m0 >= nrows) return;
    const int n0 = blockIdx.x * 64;

    const float* __restrict__ B0;
    const float* __restrict__ B1 = nullptr;
    if (MODE == 0) {
        B0 = sp ? g_w_sg : g_w_gate + (size_t)e * KD * ND;
        B1 = sp ? g_w_su : g_w_up + (size_t)e * KD * ND;
    } else {
        B0 = sp ? g_w_sd : g_w_down + (size_t)e * KD * ND;
    }
    float* __restrict__ Act = sp ? g_act_sh : (g_act_rt + (size_t)e * TT * II);

    extern __shared__ uint32_t smem[];
    const uint32_t smem_u32 = (uint32_t)__cvta_generic_to_shared(smem);

    const int tid = threadIdx.x;
    const int lane = tid & 31;
    const int warp = tid >> 5;
    const int wm = warp & 3;
    const int wn = warp >> 2;
    const int gid = lane >> 2;
    const int tig = lane & 3;

    // A: 128x32 floats = 4 float4/thread
    int asm_off[4];
    const float* aptr[4];
#pragma unroll
    for (int l = 0; l < 4; l++) {
        int gi = l * 256 + tid;
        int arow = gi >> 3;
        int acol = (gi & 7) * 4;
        asm_off[l] = arow * AW + acol;
        int r = m0 + arow;
        if (r >= nrows) r = nrows - 1;
        if (MODE == 1) {
            aptr[l] = Act + (size_t)r * II + acol;
        } else {
            int src = sp ? r : g_tok[e * TT + r];
            aptr[l] = g_x32 + (size_t)src * HH + acol;
        }
    }
    // B: 32x64 floats per matrix = 2 float4/thread per matrix
    int bsm_off[2];
    const float* b0ptr[2];
    const float* b1ptr[2];
#pragma unroll
    for (int l = 0; l < 2; l++) {
        int gi = l * 256 + tid;
        int bkr = gi >> 4;
        int bn = (gi & 15) * 4;
        bsm_off[l] = bkr * BW + bn;
        b0ptr[l] = B0 + (size_t)bkr * ND + n0 + bn;
        if (MODE == 0) b1ptr[l] = B1 + (size_t)bkr * ND + n0 + bn;
    }

    uint32_t a_addr[2];
#pragma unroll
    for (int mt = 0; mt < 2; mt++) {
        int r = wm * 32 + mt * 16 + (lane & 15);
        int c = (lane >> 4) * 4;
        a_addr[mt] = smem_u32 + (r * AW + c) * 4;
    }

    float acc0[2][4][4], acc1[2][4][4];
#pragma unroll
    for (int mt = 0; mt < 2; mt++)
#pragma unroll
        for (int nt = 0; nt < 4; nt++)
#pragma unroll
            for (int j = 0; j < 4; j++) { acc0[mt][nt][j] = 0.f; if (MODE == 0) acc1[mt][nt][j] = 0.f; }

    auto issue = [&](int kt, int slot) {
        const uint32_t sb = smem_u32 + (uint32_t)slot * STAGE * 4;
        const int k0 = kt * 32;
#pragma unroll
        for (int l = 0; l < 4; l++)
            cp_async16(sb + asm_off[l] * 4, aptr[l] + k0);
#pragma unroll
        for (int l = 0; l < 2; l++)
            cp_async16(sb + (ABUF + bsm_off[l]) * 4, b0ptr[l] + (size_t)k0 * ND);
        if (MODE == 0) {
#pragma unroll
            for (int l = 0; l < 2; l++)
                cp_async16(sb + (ABUF + BBUF + bsm_off[l]) * 4, b1ptr[l] + (size_t)k0 * ND);
        }
    };

#pragma unroll
    for (int s = 0; s < NSTAGE - 1; s++) { issue(s, s); cp_commit(); }

    int slot = 0;
    for (int kt = 0; kt < NK; kt++) {
        cp_wait<NSTAGE - 2>();
        __syncthreads();

        if (kt + NSTAGE - 1 < NK) {
            int ns = kt + NSTAGE - 1;
            issue(ns, ns % NSTAGE);
        }
        cp_commit();

        const uint32_t sbyte = (uint32_t)slot * STAGE * 4;
        const uint32_t* Bc0 = smem + slot * STAGE + ABUF;
        const uint32_t* Bc1 = Bc0 + BBUF;
#pragma unroll
        for (int ks = 0; ks < 4; ks++) {
            uint32_t a[2][4];
            ldsm4(a[0][0], a[0][1], a[0][2], a[0][3], a_addr[0] + sbyte + ks * 32);
            ldsm4(a[1][0], a[1][1], a[1][2], a[1][3], a_addr[1] + sbyte + ks * 32);

            const int kk = ks * 8 + tig;
#pragma unroll
            for (int nt = 0; nt < 4; nt++) {
                const int nn = wn * 32 + nt * 8 + gid;
                uint32_t b0a = Bc0[kk * BW + nn];
                uint32_t b0b = Bc0[(kk + 4) * BW + nn];
#pragma unroll
                for (int mt = 0; mt < 2; mt++)
                    mma_tf32(acc0[mt][nt], a[mt], b0a, b0b);
                if (MODE == 0) {
                    uint32_t b1a = Bc1[kk * BW + nn];
                    uint32_t b1b = Bc1[(kk + 4) * BW + nn];
#pragma unroll
                    for (int mt = 0; mt < 2; mt++)
                        mma_tf32(acc1[mt][nt], a[mt], b1a, b1b);
                }
            }
        }
        slot = (slot + 1 == NSTAGE) ? 0 : slot + 1;
    }

    // ---- epilogue ----
#pragma unroll
    for (int mt = 0; mt < 2; mt++) {
#pragma unroll
        for (int i = 0; i < 2; i++) {
            int rl = m0 + wm * 32 + mt * 16 + i * 8 + gid;
            if (rl >= nrows) continue;
#pragma unroll
            for (int nt = 0; nt < 4; nt++) {
                int col = n0 + wn * 32 + nt * 8 + tig * 2;
                if (MODE == 0) {
                    float g0 = acc0[mt][nt][i * 2 + 0], g1 = acc0[mt][nt][i * 2 + 1];
                    float u0 = acc1[mt][nt][i * 2 + 0], u1 = acc1[mt][nt][i * 2 + 1];
                    float s0 = u0 * (g0 / (1.f + expf(-g0)));
                    float s1 = u1 * (g1 / (1.f + expf(-g1)));
                    // store pre-rounded tf32 bits so GEMM2 needs no cvt
                    uint2 st = make_uint2(f2tf(s0), f2tf(s1));
                    *(uint2*)(Act + (size_t)rl * II + col) = st;
                } else {
                    float2 v = make_float2(acc0[mt][nt][i * 2], acc0[mt][nt][i * 2 + 1]);
                    if (sp) {
                        *(float2*)(out + (size_t)rl * HH + col) = v;
                    } else {
                        *(float2*)(g_out2 + (size_t)(e * TT + rl) * HH + col) = v;
                    }
                }
            }
        }
    }
}

// -------------------- combine: out[t] += w0*out2[s0] + w1*out2[s1] --------------------
__global__ void k_combine(float* __restrict__ out) {
    const int t = blockIdx.x;
    const int c = threadIdx.x * 4;
    const int s0 = g_tslot[t * 2 + 0], s1 = g_tslot[t * 2 + 1];
    const float w0 = g_tw[t * 2 + 0], w1 = g_tw[t * 2 + 1];
    float4 o = *(const float4*)(out + (size_t)t * HH + c);
    float4 a = *(const float4*)(g_out2 + (size_t)s0 * HH + c);
    float4 b = *(const float4*)(g_out2 + (size_t)s1 * HH + c);
    o.x += w0 * a.x + w1 * b.x;
    o.y += w0 * a.y + w1 * b.y;
    o.z += w0 * a.z + w1 * b.z;
    o.w += w0 * a.w + w1 * b.w;
    *(float4*)(out + (size_t)t * HH + c) = o;
}

// -------------------- finalize losses --------------------
__global__ void k_final(float* __restrict__ out) {
    if (threadIdx.x == 0) {
        float aux = 0.f;
        for (int e = 0; e < EE; e++) aux += (float)g_cnt[e] * g_psum[e];
        aux = aux * (float)EE / ((float)(2) * (float)TT * (float)TT);
        out[(size_t)TT * HH + 0] = aux;
        out[(size_t)TT * HH + 1] = g_zsum / (float)TT;
    }
}

// -------------------- launch --------------------
extern "C" void kernel_launch(void* const* d_in, const int* in_sizes, int n_in,
                              void* d_out, int out_size) {
    const float* x   = (const float*)d_in[0];
    const float* rw  = (const float*)d_in[1];
    const float* gw  = (const float*)d_in[2];
    const float* uw  = (const float*)d_in[3];
    const float* dw  = (const float*)d_in[4];
    const float* sgw = (const float*)d_in[5];
    const float* suw = (const float*)d_in[6];
    const float* sdw = (const float*)d_in[7];
    float* out = (float*)d_out;

    const int smem0 = NSTAGE * (ABUF + 2 * BBUF) * 4;   // 108 KB
    const int smem1 = NSTAGE * (ABUF + 1 * BBUF) * 4;   //  81 KB
    cudaFuncSetAttribute(k_gemm<0>, cudaFuncAttributeMaxDynamicSharedMemorySize, smem0);
    cudaFuncSetAttribute(k_gemm<1>, cudaFuncAttributeMaxDynamicSharedMemorySize, smem1);

    k_init<<<1, 32>>>();
    k_round<<<(N4_TOTAL + 255) / 256, 256>>>(gw, uw, dw, sgw, suw, sdw, x);
    k_router<<<TT / 4, 128>>>(x, rw, out);
    // fused gate+up: act = tf32(silu(X@Wg) * (X@Wu))
    k_gemm<0><<<dim3(II / 64, TT / 128, EE + 1), 256, smem0>>>(out);
    // down: routed -> g_out2 (slot-major), shared -> out
    k_gemm<1><<<dim3(HH / 64, TT / 128, EE + 1), 256, smem1>>>(out);
    // combine top-2 weighted routed results into out
    k_combine<<<TT, 256>>>(out);
    k_final<<<1, 32>>>(out);
}

// round 8
// speedup vs baseline: 1.4810x; 1.4810x over previous
#include <cuda_runtime.h>
#include <math.h>
#include <stdint.h>

#define TT 4096   // tokens (B*S)
#define HH 1024   // hidden
#define II 2048   // intermediate
#define EE 8      // experts
// TOP_K = 2

// -------- scratch (static device arrays: no allocs allowed) --------
__device__ int   g_cnt[EE];
__device__ float g_psum[EE];
__device__ float g_zsum;
__device__ int   g_tok[EE * TT];          // bucket -> token
__device__ int   g_tslot[TT * 2];         // token -> slot (e*TT+pos)
__device__ float g_tw[TT * 2];            // token -> normalized weight
__device__ float g_act_sh[(size_t)TT * II];          // shared-expert activations (tf32 bits)
__device__ float g_act_rt[(size_t)EE * TT * II];     // routed activations (tf32 bits)
__device__ float g_out2[(size_t)EE * TT * HH];       // routed down-proj, slot-major

// -------------------- helpers --------------------
__device__ __forceinline__ uint32_t f2tf(float f) {
    uint32_t o; asm("cvt.rna.tf32.f32 %0, %1;" : "=r"(o) : "f"(f)); return o;
}
__device__ __forceinline__ uint32_t f2tf_u(uint32_t raw) {
    return f2tf(__uint_as_float(raw));
}
__device__ __forceinline__ void ldsm4(uint32_t& r0, uint32_t& r1, uint32_t& r2, uint32_t& r3,
                                      uint32_t addr) {
    asm volatile("ldmatrix.sync.aligned.m8n8.x4.shared.b16 {%0,%1,%2,%3}, [%4];"
                 : "=r"(r0), "=r"(r1), "=r"(r2), "=r"(r3) : "r"(addr));
}
__device__ __forceinline__ void mma_tf32(float* c, const uint32_t* a, uint32_t b0, uint32_t b1) {
    asm volatile("mma.sync.aligned.m16n8k8.row.col.f32.tf32.tf32.f32 "
                 "{%0,%1,%2,%3}, {%4,%5,%6,%7}, {%8,%9}, {%0,%1,%2,%3};"
                 : "+f"(c[0]), "+f"(c[1]), "+f"(c[2]), "+f"(c[3])
                 : "r"(a[0]), "r"(a[1]), "r"(a[2]), "r"(a[3]), "r"(b0), "r"(b1));
}
__device__ __forceinline__ void cp_async16(uint32_t saddr, const void* gptr) {
    asm volatile("cp.async.cg.shared.global [%0], [%1], 16;" :: "r"(saddr), "l"(gptr));
}
__device__ __forceinline__ void cp_commit() { asm volatile("cp.async.commit_group;"); }
template<int N>
__device__ __forceinline__ void cp_wait() { asm volatile("cp.async.wait_group %0;" :: "n"(N)); }

// -------------------- init --------------------
__global__ void k_init() {
    int i = threadIdx.x;
    if (i < EE) { g_cnt[i] = 0; g_psum[i] = 0.f; }
    if (i == 0) g_zsum = 0.f;
}

// -------------------- router (full fp32 precision) --------------------
__global__ void k_router(const float* __restrict__ x, const float* __restrict__ rw,
                         float* __restrict__ out) {
    __shared__ float s_p[EE];
    __shared__ float s_z;
    if (threadIdx.x < EE) s_p[threadIdx.x] = 0.f;
    if (threadIdx.x == 0) s_z = 0.f;
    __syncthreads();

    const int warp = threadIdx.x >> 5;
    const int lane = threadIdx.x & 31;
    const int t = blockIdx.x * 4 + warp;

    float acc[EE];
#pragma unroll
    for (int e = 0; e < EE; e++) acc[e] = 0.f;
    const float* xr = x + (size_t)t * HH;
    for (int jj = 0; jj < HH / 32; jj++) {
        int j = jj * 32 + lane;
        float xv = xr[j];
        const float* r = rw + j * EE;
#pragma unroll
        for (int e = 0; e < EE; e++) acc[e] = fmaf(xv, r[e], acc[e]);
    }
#pragma unroll
    for (int e = 0; e < EE; e++) {
#pragma unroll
        for (int o = 16; o > 0; o >>= 1) acc[e] += __shfl_xor_sync(0xffffffffu, acc[e], o);
    }

    if (lane == 0) {
        float* lo = out + (size_t)TT * HH + 2 + (size_t)t * EE;
        float mx = acc[0];
#pragma unroll
        for (int e = 1; e < EE; e++) mx = fmaxf(mx, acc[e]);
        float p[EE];
        float se = 0.f;
#pragma unroll
        for (int e = 0; e < EE; e++) { p[e] = expf(acc[e] - mx); se += p[e]; }
        float lse = logf(se) + mx;
        atomicAdd(&s_z, lse * lse);
        float inv = 1.f / se;
#pragma unroll
        for (int e = 0; e < EE; e++) {
            p[e] *= inv;
            lo[e] = acc[e];
            atomicAdd(&s_p[e], p[e]);
        }
        int i0 = 0;
#pragma unroll
        for (int e = 1; e < EE; e++) if (p[e] > p[i0]) i0 = e;
        int i1 = -1;
#pragma unroll
        for (int e = 0; e < EE; e++) {
            if (e == i0) continue;
            if (i1 < 0 || p[e] > p[i1]) i1 = e;
        }
        float ws = p[i0] + p[i1];
        float w0 = p[i0] / ws, w1 = p[i1] / ws;
        int pos0 = atomicAdd(&g_cnt[i0], 1);
        g_tok[i0 * TT + pos0] = t;
        g_tslot[t * 2 + 0] = i0 * TT + pos0; g_tw[t * 2 + 0] = w0;
        int pos1 = atomicAdd(&g_cnt[i1], 1);
        g_tok[i1 * TT + pos1] = t;
        g_tslot[t * 2 + 1] = i1 * TT + pos1; g_tw[t * 2 + 1] = w1;
    }
    __syncthreads();
    if (threadIdx.x < EE) atomicAdd(&g_psum[threadIdx.x], s_p[threadIdx.x]);
    if (threadIdx.x == 0) atomicAdd(&g_zsum, s_z);
}

// ==================== tf32 GEMM, 3-stage cp.async + fragment double-buffer ====
// BM=128, BN=64, BK=32. 256 threads = 8 warps (4m x 2n), warp tile 32x32.
// MODE 0: fused gate+up — A = x (fp32, cvt at frag load), B0 = gate_w, B1 = up_w,
//         epilogue silu(g)*u stored as tf32 bits -> act buf.
// MODE 1: down — A = act buf (already tf32 bits, NO cvt), B0 = down_w,
//         z<8: store g_out2 slot-major; z==8: store out.
#define AW 36
#define BW 72
#define ABUF (128 * AW)
#define BBUF (32 * BW)
#define NSTAGE 3

template<int MODE>
__global__ __launch_bounds__(256, 2) void k_gemm(
    const float* __restrict__ x,
    const float* __restrict__ ew0, const float* __restrict__ ew1,
    const float* __restrict__ sw0, const float* __restrict__ sw1,
    float* __restrict__ out)
{
    constexpr int KD = (MODE == 1) ? II : HH;
    constexpr int ND = (MODE == 1) ? HH : II;
    constexpr int NK = KD / 32;
    constexpr int NB = (MODE == 0) ? 2 : 1;
    constexpr int STAGE = ABUF + NB * BBUF;

    const int e = blockIdx.z;
    const bool sp = (e == EE);
    const int nrows = sp ? TT : g_cnt[e];
    const int m0 = blockIdx.y * 128;
    if (m0 >= nrows) return;
    const int n0 = blockIdx.x * 64;

    const float* __restrict__ B0;
    const float* __restrict__ B1 = nullptr;
    if (MODE == 0) {
        B0 = sp ? sw0 : ew0 + (size_t)e * KD * ND;
        B1 = sp ? sw1 : ew1 + (size_t)e * KD * ND;
    } else {
        B0 = sp ? sw0 : ew0 + (size_t)e * KD * ND;
    }
    float* __restrict__ Act = sp ? g_act_sh : (g_act_rt + (size_t)e * TT * II);

    extern __shared__ uint32_t smem[];
    const uint32_t smem_u32 = (uint32_t)__cvta_generic_to_shared(smem);

    const int tid = threadIdx.x;
    const int lane = tid & 31;
    const int warp = tid >> 5;
    const int wm = warp & 3;
    const int wn = warp >> 2;
    const int gid = lane >> 2;
    const int tig = lane & 3;

    // A: 128x32 floats = 4 float4/thread
    int asm_off[4];
    const float* aptr[4];
#pragma unroll
    for (int l = 0; l < 4; l++) {
        int gi = l * 256 + tid;
        int arow = gi >> 3;
        int acol = (gi & 7) * 4;
        asm_off[l] = arow * AW + acol;
        int r = m0 + arow;
        if (r >= nrows) r = nrows - 1;
        if (MODE == 1) {
            aptr[l] = Act + (size_t)r * II + acol;
        } else {
            int src = sp ? r : g_tok[e * TT + r];
            aptr[l] = x + (size_t)src * HH + acol;
        }
    }
    // B: 32x64 floats per matrix = 2 float4/thread per matrix
    int bsm_off[2];
    const float* b0ptr[2];
    const float* b1ptr[2];
#pragma unroll
    for (int l = 0; l < 2; l++) {
        int gi = l * 256 + tid;
        int bkr = gi >> 4;
        int bn = (gi & 15) * 4;
        bsm_off[l] = bkr * BW + bn;
        b0ptr[l] = B0 + (size_t)bkr * ND + n0 + bn;
        if (MODE == 0) b1ptr[l] = B1 + (size_t)bkr * ND + n0 + bn;
    }

    uint32_t a_addr[2];
#pragma unroll
    for (int mt = 0; mt < 2; mt++) {
        int r = wm * 32 + mt * 16 + (lane & 15);
        int c = (lane >> 4) * 4;
        a_addr[mt] = smem_u32 + (r * AW + c) * 4;
    }

    float acc0[2][4][4], acc1[2][4][4];
#pragma unroll
    for (int mt = 0; mt < 2; mt++)
#pragma unroll
        for (int nt = 0; nt < 4; nt++)
#pragma unroll
            for (int j = 0; j < 4; j++) { acc0[mt][nt][j] = 0.f; if (MODE == 0) acc1[mt][nt][j] = 0.f; }

    auto issue = [&](int kt, int slot) {
        const uint32_t sb = smem_u32 + (uint32_t)slot * STAGE * 4;
        const int k0 = kt * 32;
#pragma unroll
        for (int l = 0; l < 4; l++)
            cp_async16(sb + asm_off[l] * 4, aptr[l] + k0);
#pragma unroll
        for (int l = 0; l < 2; l++)
            cp_async16(sb + (ABUF + bsm_off[l]) * 4, b0ptr[l] + (size_t)k0 * ND);
        if (MODE == 0) {
#pragma unroll
            for (int l = 0; l < 2; l++)
                cp_async16(sb + (ABUF + BBUF + bsm_off[l]) * 4, b1ptr[l] + (size_t)k0 * ND);
        }
    };

#pragma unroll
    for (int s = 0; s < NSTAGE - 1; s++) { issue(s, s); cp_commit(); }

    // fragment double buffers
    uint32_t af[2][2][4];
    uint32_t bf0[2][4][2];
    uint32_t bf1[2][4][2];

    int slot = 0;
    for (int kt = 0; kt < NK; kt++) {
        cp_wait<NSTAGE - 2>();
        __syncthreads();

        if (kt + NSTAGE - 1 < NK) {
            int ns = kt + NSTAGE - 1;
            issue(ns, ns % NSTAGE);
        }
        cp_commit();

        const uint32_t sbyte = (uint32_t)slot * STAGE * 4;
        const uint32_t* Bc0 = smem + slot * STAGE + ABUF;
        const uint32_t* Bc1 = Bc0 + BBUF;

        // fragment loader for k-slice ks into parity p
        auto lfrag = [&](int ks, int p) {
            ldsm4(af[p][0][0], af[p][0][1], af[p][0][2], af[p][0][3],
                  a_addr[0] + sbyte + ks * 32);
            ldsm4(af[p][1][0], af[p][1][1], af[p][1][2], af[p][1][3],
                  a_addr[1] + sbyte + ks * 32);
            if (MODE == 0) {
#pragma unroll
                for (int mt = 0; mt < 2; mt++)
#pragma unroll
                    for (int j = 0; j < 4; j++) af[p][mt][j] = f2tf_u(af[p][mt][j]);
            }
            const int kk = ks * 8 + tig;
#pragma unroll
            for (int nt = 0; nt < 4; nt++) {
                const int nn = wn * 32 + nt * 8 + gid;
                bf0[p][nt][0] = f2tf_u(Bc0[kk * BW + nn]);
                bf0[p][nt][1] = f2tf_u(Bc0[(kk + 4) * BW + nn]);
                if (MODE == 0) {
                    bf1[p][nt][0] = f2tf_u(Bc1[kk * BW + nn]);
                    bf1[p][nt][1] = f2tf_u(Bc1[(kk + 4) * BW + nn]);
                }
            }
        };

        lfrag(0, 0);
#pragma unroll
        for (int ks = 0; ks < 4; ks++) {
            const int p = ks & 1;
            if (ks < 3) lfrag(ks + 1, p ^ 1);
#pragma unroll
            for (int nt = 0; nt < 4; nt++) {
#pragma unroll
                for (int mt = 0; mt < 2; mt++) {
                    mma_tf32(acc0[mt][nt], af[p][mt], bf0[p][nt][0], bf0[p][nt][1]);
                    if (MODE == 0)
                        mma_tf32(acc1[mt][nt], af[p][mt], bf1[p][nt][0], bf1[p][nt][1]);
                }
            }
        }
        slot = (slot + 1 == NSTAGE) ? 0 : slot + 1;
    }

    // ---- epilogue ----
#pragma unroll
    for (int mt = 0; mt < 2; mt++) {
#pragma unroll
        for (int i = 0; i < 2; i++) {
            int rl = m0 + wm * 32 + mt * 16 + i * 8 + gid;
            if (rl >= nrows) continue;
#pragma unroll
            for (int nt = 0; nt < 4; nt++) {
                int col = n0 + wn * 32 + nt * 8 + tig * 2;
                if (MODE == 0) {
                    float g0 = acc0[mt][nt][i * 2 + 0], g1 = acc0[mt][nt][i * 2 + 1];
                    float u0 = acc1[mt][nt][i * 2 + 0], u1 = acc1[mt][nt][i * 2 + 1];
                    float s0 = u0 * (g0 / (1.f + expf(-g0)));
                    float s1 = u1 * (g1 / (1.f + expf(-g1)));
                    // store tf32 bit patterns so GEMM2 needs no A-side cvt
                    uint2 st = make_uint2(f2tf(s0), f2tf(s1));
                    *(uint2*)(Act + (size_t)rl * II + col) = st;
                } else {
                    float2 v = make_float2(acc0[mt][nt][i * 2], acc0[mt][nt][i * 2 + 1]);
                    if (sp) {
                        *(float2*)(out + (size_t)rl * HH + col) = v;
                    } else {
                        *(float2*)(g_out2 + (size_t)(e * TT + rl) * HH + col) = v;
                    }
                }
            }
        }
    }
}

// -------------------- combine: out[t] += w0*out2[s0] + w1*out2[s1] --------------------
__global__ void k_combine(float* __restrict__ out) {
    const int t = blockIdx.x;
    const int c = threadIdx.x * 4;
    const int s0 = g_tslot[t * 2 + 0], s1 = g_tslot[t * 2 + 1];
    const float w0 = g_tw[t * 2 + 0], w1 = g_tw[t * 2 + 1];
    float4 o = *(const float4*)(out + (size_t)t * HH + c);
    float4 a = *(const float4*)(g_out2 + (size_t)s0 * HH + c);
    float4 b = *(const float4*)(g_out2 + (size_t)s1 * HH + c);
    o.x += w0 * a.x + w1 * b.x;
    o.y += w0 * a.y + w1 * b.y;
    o.z += w0 * a.z + w1 * b.z;
    o.w += w0 * a.w + w1 * b.w;
    *(float4*)(out + (size_t)t * HH + c) = o;
}

// -------------------- finalize losses --------------------
__global__ void k_final(float* __restrict__ out) {
    if (threadIdx.x == 0) {
        float aux = 0.f;
        for (int e = 0; e < EE; e++) aux += (float)g_cnt[e] * g_psum[e];
        aux = aux * (float)EE / ((float)(2) * (float)TT * (float)TT);
        out[(size_t)TT * HH + 0] = aux;
        out[(size_t)TT * HH + 1] = g_zsum / (float)TT;
    }
}

// -------------------- launch --------------------
extern "C" void kernel_launch(void* const* d_in, const int* in_sizes, int n_in,
                              void* d_out, int out_size) {
    const float* x   = (const float*)d_in[0];
    const float* rw  = (const float*)d_in[1];
    const float* gw  = (const float*)d_in[2];
    const float* uw  = (const float*)d_in[3];
    const float* dw  = (const float*)d_in[4];
    const float* sgw = (const float*)d_in[5];
    const float* suw = (const float*)d_in[6];
    const float* sdw = (const float*)d_in[7];
    float* out = (float*)d_out;

    const int smem0 = NSTAGE * (ABUF + 2 * BBUF) * 4;   // 108 KB
    const int smem1 = NSTAGE * (ABUF + 1 * BBUF) * 4;   //  81 KB
    cudaFuncSetAttribute(k_gemm<0>, cudaFuncAttributeMaxDynamicSharedMemorySize, smem0);
    cudaFuncSetAttribute(k_gemm<1>, cudaFuncAttributeMaxDynamicSharedMemorySize, smem1);

    k_init<<<1, 32>>>();
    k_router<<<TT / 4, 128>>>(x, rw, out);
    // fused gate+up: act = tf32(silu(X@Wg) * (X@Wu))
    k_gemm<0><<<dim3(II / 64, TT / 128, EE + 1), 256, smem0>>>(x, gw, uw, sgw, suw, out);
    // down: routed -> g_out2 (slot-major), shared -> out
    k_gemm<1><<<dim3(HH / 64, TT / 128, EE + 1), 256, smem1>>>(x, dw, nullptr, sdw, nullptr, out);
    // combine top-2 weighted routed results into out
    k_combine<<<TT, 256>>>(out);
    k_final<<<1, 32>>>(out);
}